// round 1
// baseline (speedup 1.0000x reference)
#include <cuda_runtime.h>
#include <math.h>

// Problem constants (fixed by setup_inputs)
#define NMAX   20000
#define EMAX   320000
#define DIN    512
#define D      256
#define NREL   6
#define NTYPE  8

// ---------------- scratch (static device globals; no allocs) ----------------
__device__ float g_h  [NMAX * D];                 // h after adapt / layer ping
__device__ float g_h2 [NMAX * D];                 // layer pong
__device__ float g_tmp[(size_t)NREL * NMAX * D];  // per-relation aggregation
__device__ float g_Wt [NTYPE * DIN * D];          // adapt_W transposed [t][k][e]
__device__ float g_inv[NMAX];
__device__ int   g_deg[NMAX];
__device__ int   g_cnt[NTYPE];
__device__ int   g_off[NTYPE + 1];
__device__ int   g_cur[NTYPE];
__device__ int   g_order[NMAX];

// ---------------- small prep kernels ----------------
__global__ void k_init(int Nn) {
    int i = blockIdx.x * 256 + threadIdx.x;
    if (i < Nn)    g_deg[i] = 0;
    if (i < NTYPE) g_cnt[i] = 0;
}

__global__ void k_count(const int* __restrict__ ei, int E_) {
    int e = blockIdx.x * 256 + threadIdx.x;
    if (e < E_) atomicAdd(&g_deg[ei[E_ + e]], 1);   // dst row
}

__global__ void k_hist(const int* __restrict__ nt, int Nn) {
    int i = blockIdx.x * 256 + threadIdx.x;
    if (i < Nn) atomicAdd(&g_cnt[nt[i]], 1);
}

__global__ void k_inv(int Nn) {
    int i = blockIdx.x * 256 + threadIdx.x;
    if (i < Nn) g_inv[i] = 1.0f / fmaxf((float)g_deg[i], 1.0f);
}

__global__ void k_offs() {
    int s = 0;
    for (int t = 0; t < NTYPE; t++) { g_off[t] = s; g_cur[t] = s; s += g_cnt[t]; }
    g_off[NTYPE] = s;
}

__global__ void k_order(const int* __restrict__ nt, int Nn) {
    int i = blockIdx.x * 256 + threadIdx.x;
    if (i < Nn) {
        int pos = atomicAdd(&g_cur[nt[i]], 1);
        g_order[pos] = i;
    }
}

// adapt_W is [t][e][k]; we want [t][k][e] so GEMM B loads are coalesced
__global__ void k_transW(const float* __restrict__ W) {
    int idx = blockIdx.x * 256 + threadIdx.x;
    if (idx < NTYPE * DIN * D) {
        int t = idx / (DIN * D);
        int r = idx % (DIN * D);
        int k = r / D;
        int e = r % D;
        g_Wt[idx] = W[((size_t)t * D + e) * DIN + k];
    }
}

__global__ void k_zero_tmp(int total4) {
    int    i      = blockIdx.x * blockDim.x + threadIdx.x;
    int    stride = gridDim.x * blockDim.x;
    float4 z      = make_float4(0.f, 0.f, 0.f, 0.f);
    float4* p     = (float4*)g_tmp;
    for (; i < total4; i += stride) p[i] = z;
}

// ---------------- edge scatter: tmp[rel][dst] += h[src] * inv_deg[dst] -------
// one warp per edge; 8 coalesced scalar atomics per lane (256 floats/edge)
__global__ void k_scatter(const int* __restrict__ ei, const int* __restrict__ et,
                          const float* __restrict__ hin, int E_, int Nn) {
    int gw   = (blockIdx.x * blockDim.x + threadIdx.x) >> 5;
    int lane = threadIdx.x & 31;
    if (gw >= E_) return;
    int   src = ei[gw];
    int   dst = ei[E_ + gw];
    int   r   = et[gw];
    float s   = g_inv[dst];
    const float* hp = hin + (size_t)src * D;
    float*       o  = g_tmp + ((size_t)r * Nn + dst) * D;
#pragma unroll
    for (int j = 0; j < 8; j++) {
        int idx = j * 32 + lane;                      // 128B-coalesced per warp inst
        atomicAdd(&o[idx], hp[idx] * s);
    }
}

// ---------------- adapt GEMM: h = tanh(X @ W_t^T + b_t), grouped by type -----
// block tile: 64 rows x 128 cols, K = 512 in chunks of 16
__global__ __launch_bounds__(256, 2)
void adapt_gemm(const float* __restrict__ X, const float* __restrict__ bias, int Nn) {
    __shared__ float As[16][68];
    __shared__ float Bs[16][132];
    __shared__ int   nid[64];

    int t    = blockIdx.z;
    int base = g_off[t];
    int cntv = g_off[t + 1] - base;
    int m0   = blockIdx.y * 64;
    if (m0 >= cntv) return;
    int e0   = blockIdx.x * 128;

    int tid = threadIdx.x;
    if (tid < 64) {
        int idx = m0 + tid;
        nid[tid] = (idx < cntv) ? g_order[base + idx] : g_order[base];
    }
    __syncthreads();

    int tx = tid & 15, ty = tid >> 4;
    int lkk = tid & 15, lm = tid >> 4;
    float acc[4][8];
#pragma unroll
    for (int i = 0; i < 4; i++)
#pragma unroll
        for (int j = 0; j < 8; j++) acc[i][j] = 0.f;

    const float* Wt = g_Wt + (size_t)t * DIN * D;

    for (int k0 = 0; k0 < DIN; k0 += 16) {
#pragma unroll
        for (int p = 0; p < 4; p++) {
            int m = lm + p * 16;
            As[lkk][m] = X[(size_t)nid[m] * DIN + k0 + lkk];
        }
#pragma unroll
        for (int p = 0; p < 2; p++) {
            int q = tid + p * 256;
            int e4 = q & 31, kk = q >> 5;
            *(float4*)&Bs[kk][e4 * 4] =
                *(const float4*)(Wt + (size_t)(k0 + kk) * D + e0 + e4 * 4);
        }
        __syncthreads();
#pragma unroll
        for (int kk = 0; kk < 16; kk++) {
            float a[4], b[8];
            *(float4*)&a[0] = *(const float4*)&As[kk][ty * 4];
            *(float4*)&b[0] = *(const float4*)&Bs[kk][tx * 8];
            *(float4*)&b[4] = *(const float4*)&Bs[kk][tx * 8 + 4];
#pragma unroll
            for (int i = 0; i < 4; i++)
#pragma unroll
                for (int j = 0; j < 8; j++) acc[i][j] += a[i] * b[j];
        }
        __syncthreads();
    }

#pragma unroll
    for (int i = 0; i < 4; i++) {
        int mi = m0 + ty * 4 + i;
        if (mi >= cntv) continue;
        int node = nid[ty * 4 + i];
#pragma unroll
        for (int j = 0; j < 8; j++) {
            int e = e0 + tx * 8 + j;
            g_h[(size_t)node * D + e] = tanhf(acc[i][j] + bias[t * D + e]);
        }
    }
}

// ---------------- fused layer GEMM ----------------
// out[n,:] = relu( [tmp_0(n)|...|tmp_5(n)|h(n)] @ [W_rel_l ; W_self_l] + b_self_l )
// K = 6*256 + 256 = 1792. block tile 128x128, chunk 16, 8x8 micro-tile.
__global__ __launch_bounds__(256, 2)
void gemm_layer(const float* __restrict__ hin, const float* __restrict__ Wrel,
                const float* __restrict__ Wself, const float* __restrict__ bself,
                float* __restrict__ hout, int Nn) {
    __shared__ float As[16][132];
    __shared__ float Bs[16][132];

    int tid = threadIdx.x;
    int tx = tid & 15, ty = tid >> 4;
    int m0 = blockIdx.y * 128;
    int e0 = blockIdx.x * 128;
    int lkk = tid & 15, lm = tid >> 4;

    float acc[8][8];
#pragma unroll
    for (int i = 0; i < 8; i++)
#pragma unroll
        for (int j = 0; j < 8; j++) acc[i][j] = 0.f;

    const int KREL = NREL * D;           // 1536
    const int KTOT = KREL + D;           // 1792

    for (int k0 = 0; k0 < KTOT; k0 += 16) {
        const float* abase;
        const float* bbase;
        if (k0 < KREL) {
            abase = g_tmp + (size_t)(k0 >> 8) * Nn * D + (k0 & 255);
            bbase = Wrel + (size_t)k0 * D + e0;
        } else {
            abase = hin + (k0 - KREL);
            bbase = Wself + (size_t)(k0 - KREL) * D + e0;
        }
#pragma unroll
        for (int p = 0; p < 8; p++) {
            int m   = lm + p * 16;
            int row = m0 + m;
            if (row > Nn - 1) row = Nn - 1;
            As[lkk][m] = abase[(size_t)row * D + lkk];
        }
#pragma unroll
        for (int p = 0; p < 2; p++) {
            int q = tid + p * 256;
            int e4 = q & 31, kk = q >> 5;
            *(float4*)&Bs[kk][e4 * 4] = *(const float4*)(bbase + (size_t)kk * D + e4 * 4);
        }
        __syncthreads();
#pragma unroll
        for (int kk = 0; kk < 16; kk++) {
            float a[8], b[8];
            *(float4*)&a[0] = *(const float4*)&As[kk][ty * 8];
            *(float4*)&a[4] = *(const float4*)&As[kk][ty * 8 + 4];
            *(float4*)&b[0] = *(const float4*)&Bs[kk][tx * 8];
            *(float4*)&b[4] = *(const float4*)&Bs[kk][tx * 8 + 4];
#pragma unroll
            for (int i = 0; i < 8; i++)
#pragma unroll
                for (int j = 0; j < 8; j++) acc[i][j] += a[i] * b[j];
        }
        __syncthreads();
    }

#pragma unroll
    for (int i = 0; i < 8; i++) {
        int m = m0 + ty * 8 + i;
        if (m >= Nn) break;
#pragma unroll
        for (int j = 0; j < 8; j++) {
            int e = e0 + tx * 8 + j;
            float v = acc[i][j] + bself[e];
            hout[(size_t)m * D + e] = v > 0.f ? v : 0.f;
        }
    }
}

// ---------------- launch ----------------
extern "C" void kernel_launch(void* const* d_in, const int* in_sizes, int n_in,
                              void* d_out, int out_size) {
    const float* X     = (const float*)d_in[0];
    const int*   ntype = (const int*)d_in[1];
    const int*   ei    = (const int*)d_in[2];
    const int*   et    = (const int*)d_in[3];
    const float* aW    = (const float*)d_in[5];
    const float* ab    = (const float*)d_in[6];
    const float* Wrel  = (const float*)d_in[7];
    const float* Wself = (const float*)d_in[8];
    const float* bself = (const float*)d_in[9];
    float*       out   = (float*)d_out;

    int Nn = in_sizes[1];
    int E_ = in_sizes[3];

    void *ph = nullptr, *ph2 = nullptr;
    cudaGetSymbolAddress(&ph,  g_h);
    cudaGetSymbolAddress(&ph2, g_h2);

    int nb = (Nn + 255) / 256;
    k_init <<<nb, 256>>>(Nn);
    k_count<<<(E_ + 255) / 256, 256>>>(ei, E_);
    k_hist <<<nb, 256>>>(ntype, Nn);
    k_inv  <<<nb, 256>>>(Nn);
    k_offs <<<1, 1>>>();
    k_order<<<nb, 256>>>(ntype, Nn);
    k_transW<<<(NTYPE * DIN * D + 255) / 256, 256>>>(aW);

    adapt_gemm<<<dim3(2, (Nn + 63) / 64, NTYPE), 256>>>(X, ab, Nn);

    int total4 = NREL * Nn * (D / 4);
    for (int l = 0; l < 2; l++) {
        const float* hin  = (l == 0) ? (const float*)ph : (const float*)ph2;
        float*       hout = (l == 0) ? (float*)ph2 : out;
        k_zero_tmp<<<4096, 256>>>(total4);
        k_scatter<<<(E_ + 7) / 8, 256>>>(ei, et, hin, E_, Nn);
        gemm_layer<<<dim3(2, (Nn + 127) / 128), 256>>>(
            hin,
            Wrel + (size_t)l * NREL * D * D,
            Wself + (size_t)l * D * D,
            bself + (size_t)l * D,
            hout, Nn);
    }
}

// round 4
// speedup vs baseline: 1.7358x; 1.7358x over previous
#include <cuda_runtime.h>
#include <cuda_bf16.h>
#include <math.h>
#include <stdint.h>

// Problem constants (fixed by setup_inputs)
#define NMAX   20000
#define EMAX   320000
#define DIN    512
#define D      256
#define NREL   6
#define NTYPE  8
#define KREL   (NREL * D)         // 1536
#define KTOT   (KREL + D)         // 1792
#define NCHUNK (KTOT / 64)        // 28

// ---------------- scratch (static device globals; no allocs) ----------------
__device__ float g_h  [NMAX * D];
__device__ float g_h2 [NMAX * D];
__device__ float g_tmp[(size_t)NREL * NMAX * D];
__device__ float g_Wt [NTYPE * DIN * D];
__device__ float g_inv[NMAX];
__device__ int   g_deg[NMAX];
__device__ int   g_cnt[NTYPE];
__device__ int   g_off[NTYPE + 1];
__device__ int   g_cur[NTYPE];
__device__ int   g_order[NMAX];
// A prepacked per layer: [m][KTOT] bf16 hi / lo
__device__ __nv_bfloat16 g_Ah[(size_t)NMAX * KTOT];
__device__ __nv_bfloat16 g_Al[(size_t)NMAX * KTOT];
// B prepacked: [layer][n=256][k=1792] bf16 hi / lo  (col-major for mma .col)
__device__ __nv_bfloat16 g_Bh[2 * 256 * KTOT];
__device__ __nv_bfloat16 g_Bl[2 * 256 * KTOT];

// ---------------- helpers ----------------
__device__ __forceinline__ uint32_t smem_u32(const void* p) {
    uint32_t a;
    asm("{ .reg .u64 t; cvta.to.shared.u64 t, %1; cvt.u32.u64 %0, t; }" : "=r"(a) : "l"(p));
    return a;
}
__device__ __forceinline__ unsigned short f2bf(float f) {
    unsigned short u;
    asm("{ .reg .b16 t; cvt.rn.bf16.f32 t, %1; mov.b16 %0, t; }" : "=h"(u) : "f"(f));
    return u;
}
__device__ __forceinline__ float bfbits2f(unsigned short u) {
    return __uint_as_float(((uint32_t)u) << 16);
}
__device__ __forceinline__ void mma_bf16(float* c, const uint32_t* a, uint32_t b0, uint32_t b1) {
    asm volatile(
        "mma.sync.aligned.m16n8k16.row.col.f32.bf16.bf16.f32 "
        "{%0,%1,%2,%3}, {%4,%5,%6,%7}, {%8,%9}, {%0,%1,%2,%3};"
        : "+f"(c[0]), "+f"(c[1]), "+f"(c[2]), "+f"(c[3])
        : "r"(a[0]), "r"(a[1]), "r"(a[2]), "r"(a[3]), "r"(b0), "r"(b1));
}
#define CP_ASYNC16(dst, src) \
    asm volatile("cp.async.cg.shared.global [%0], [%1], 16;" :: "r"(dst), "l"(src) : "memory")
#define CP_COMMIT()  asm volatile("cp.async.commit_group;" ::: "memory")
#define CP_WAIT1()   asm volatile("cp.async.wait_group 1;" ::: "memory")
#define CP_WAIT0()   asm volatile("cp.async.wait_group 0;" ::: "memory")

// ---------------- small prep kernels ----------------
__global__ void k_init(int Nn) {
    int i = blockIdx.x * 256 + threadIdx.x;
    if (i < Nn)    g_deg[i] = 0;
    if (i < NTYPE) g_cnt[i] = 0;
}
__global__ void k_count(const int* __restrict__ ei, int E_) {
    int e = blockIdx.x * 256 + threadIdx.x;
    if (e < E_) atomicAdd(&g_deg[ei[E_ + e]], 1);
}
__global__ void k_hist(const int* __restrict__ nt, int Nn) {
    int i = blockIdx.x * 256 + threadIdx.x;
    if (i < Nn) atomicAdd(&g_cnt[nt[i]], 1);
}
__global__ void k_inv(int Nn) {
    int i = blockIdx.x * 256 + threadIdx.x;
    if (i < Nn) g_inv[i] = 1.0f / fmaxf((float)g_deg[i], 1.0f);
}
__global__ void k_offs() {
    int s = 0;
    for (int t = 0; t < NTYPE; t++) { g_off[t] = s; g_cur[t] = s; s += g_cnt[t]; }
    g_off[NTYPE] = s;
}
__global__ void k_order(const int* __restrict__ nt, int Nn) {
    int i = blockIdx.x * 256 + threadIdx.x;
    if (i < Nn) {
        int pos = atomicAdd(&g_cur[nt[i]], 1);
        g_order[pos] = i;
    }
}
__global__ void k_transW(const float* __restrict__ W) {
    int idx = blockIdx.x * 256 + threadIdx.x;
    if (idx < NTYPE * DIN * D) {
        int t = idx / (DIN * D);
        int r = idx % (DIN * D);
        int k = r / D;
        int e = r % D;
        g_Wt[idx] = W[((size_t)t * D + e) * DIN + k];
    }
}
__global__ void k_zero_tmp(int total4) {
    int    i      = blockIdx.x * blockDim.x + threadIdx.x;
    int    stride = gridDim.x * blockDim.x;
    float4 z      = make_float4(0.f, 0.f, 0.f, 0.f);
    float4* p     = (float4*)g_tmp;
    for (; i < total4; i += stride) p[i] = z;
}

// pack B = [Wrel_l ; Wself_l] transposed to [l][e][k] bf16 hi/lo
__global__ void k_packB(const float* __restrict__ Wrel, const float* __restrict__ Wself) {
    int idx = blockIdx.x * 256 + threadIdx.x;
    if (idx >= 2 * 256 * KTOT) return;
    int l    = idx / (256 * KTOT);
    int rest = idx % (256 * KTOT);
    int e    = rest / KTOT;
    int k    = rest % KTOT;
    float w;
    if (k < KREL) w = Wrel[(((size_t)l * NREL + (k >> 8)) * D + (k & 255)) * D + e];
    else          w = Wself[((size_t)l * D + (k - KREL)) * D + e];
    unsigned short hi = f2bf(w);
    unsigned short lo = f2bf(w - bfbits2f(hi));
    *reinterpret_cast<unsigned short*>(&g_Bh[idx]) = hi;
    *reinterpret_cast<unsigned short*>(&g_Bl[idx]) = lo;
}

// convert A = [tmp_0..5 | hin] fp32 -> bf16 hi/lo, layout [m][KTOT]
__global__ void k_convA(const float* __restrict__ hin, int Nn) {
    int i4 = blockIdx.x * 256 + threadIdx.x;         // float4 index
    int total4 = Nn * (KTOT / 4);
    if (i4 >= total4) return;
    int m  = i4 / (KTOT / 4);
    int kq = i4 % (KTOT / 4);
    int k  = kq * 4;
    const float* src = (k < KREL)
        ? &g_tmp[((size_t)(k >> 8) * Nn + m) * D + (k & 255)]
        : &hin[(size_t)m * D + (k - KREL)];
    float4 v = *(const float4*)src;
    unsigned short h0 = f2bf(v.x), h1 = f2bf(v.y), h2 = f2bf(v.z), h3 = f2bf(v.w);
    unsigned short l0 = f2bf(v.x - bfbits2f(h0));
    unsigned short l1 = f2bf(v.y - bfbits2f(h1));
    unsigned short l2 = f2bf(v.z - bfbits2f(h2));
    unsigned short l3 = f2bf(v.w - bfbits2f(h3));
    uint2 hv = make_uint2((uint32_t)h0 | ((uint32_t)h1 << 16), (uint32_t)h2 | ((uint32_t)h3 << 16));
    uint2 lv = make_uint2((uint32_t)l0 | ((uint32_t)l1 << 16), (uint32_t)l2 | ((uint32_t)l3 << 16));
    *(uint2*)&g_Ah[(size_t)m * KTOT + k] = hv;
    *(uint2*)&g_Al[(size_t)m * KTOT + k] = lv;
}

// ---------------- edge scatter ----------------
__global__ void k_scatter(const int* __restrict__ ei, const int* __restrict__ et,
                          const float* __restrict__ hin, int E_, int Nn) {
    int gw   = (blockIdx.x * blockDim.x + threadIdx.x) >> 5;
    int lane = threadIdx.x & 31;
    if (gw >= E_) return;
    int   src = ei[gw];
    int   dst = ei[E_ + gw];
    int   r   = et[gw];
    float s   = g_inv[dst];
    const float* hp = hin + (size_t)src * D;
    float*       o  = g_tmp + ((size_t)r * Nn + dst) * D;
#pragma unroll
    for (int j = 0; j < 8; j++) {
        int idx = j * 32 + lane;
        atomicAdd(&o[idx], hp[idx] * s);
    }
}

// ---------------- adapt GEMM (fp32 SIMT, passing) ----------------
__global__ __launch_bounds__(256, 2)
void adapt_gemm(const float* __restrict__ X, const float* __restrict__ bias, int Nn) {
    __shared__ float As[16][68];
    __shared__ float Bs[16][132];
    __shared__ int   nid[64];

    int t    = blockIdx.z;
    int base = g_off[t];
    int cntv = g_off[t + 1] - base;
    int m0   = blockIdx.y * 64;
    if (m0 >= cntv) return;
    int e0   = blockIdx.x * 128;

    int tid = threadIdx.x;
    if (tid < 64) {
        int idx = m0 + tid;
        nid[tid] = (idx < cntv) ? g_order[base + idx] : g_order[base];
    }
    __syncthreads();

    int tx = tid & 15, ty = tid >> 4;
    int lkk = tid & 15, lm = tid >> 4;
    float acc[4][8];
#pragma unroll
    for (int i = 0; i < 4; i++)
#pragma unroll
        for (int j = 0; j < 8; j++) acc[i][j] = 0.f;

    const float* Wt = g_Wt + (size_t)t * DIN * D;

    for (int k0 = 0; k0 < DIN; k0 += 16) {
#pragma unroll
        for (int p = 0; p < 4; p++) {
            int m = lm + p * 16;
            As[lkk][m] = X[(size_t)nid[m] * DIN + k0 + lkk];
        }
#pragma unroll
        for (int p = 0; p < 2; p++) {
            int q = tid + p * 256;
            int e4 = q & 31, kk = q >> 5;
            *(float4*)&Bs[kk][e4 * 4] =
                *(const float4*)(Wt + (size_t)(k0 + kk) * D + e0 + e4 * 4);
        }
        __syncthreads();
#pragma unroll
        for (int kk = 0; kk < 16; kk++) {
            float a[4], b[8];
            *(float4*)&a[0] = *(const float4*)&As[kk][ty * 4];
            *(float4*)&b[0] = *(const float4*)&Bs[kk][tx * 8];
            *(float4*)&b[4] = *(const float4*)&Bs[kk][tx * 8 + 4];
#pragma unroll
            for (int i = 0; i < 4; i++)
#pragma unroll
                for (int j = 0; j < 8; j++) acc[i][j] += a[i] * b[j];
        }
        __syncthreads();
    }

#pragma unroll
    for (int i = 0; i < 4; i++) {
        int mi = m0 + ty * 4 + i;
        if (mi >= cntv) continue;
        int node = nid[ty * 4 + i];
#pragma unroll
        for (int j = 0; j < 8; j++) {
            int e = e0 + tx * 8 + j;
            g_h[(size_t)node * D + e] = tanhf(acc[i][j] + bias[t * D + e]);
        }
    }
}

// ---------------- tensor-core (mma.sync bf16) fused layer GEMM ----------------
// out = relu( A(128 x 1792) @ B(1792 x 128-block) + b ), 3-product bf16 split.
// SMEM: 4 arrays [128 rows][72 els bf16] (Ahi, Alo, Bhi, Blo), double-buffered.
#define ROWP   72                       // padded row length (elements)
#define ARR_B  (128 * ROWP * 2)         // 18432 bytes per array
#define BUF_B  (4 * ARR_B)              // 73728 per buffer
#define SMEM_TOTAL (2 * BUF_B)          // 147456

__global__ __launch_bounds__(256, 1)
void gemm_layer_mma(const float* __restrict__ bself, float* __restrict__ hout,
                    int Nn, int layer) {
    extern __shared__ char smem[];
    uint32_t sb = smem_u32(smem);
    int tid  = threadIdx.x;
    int wid  = tid >> 5;
    int lane = tid & 31;
    int g    = lane >> 2;          // groupID
    int tig  = lane & 3;           // thread-in-group
    int wm   = wid & 3;            // warp m-tile (4 x 32 rows)
    int wn   = wid >> 2;           // warp n-tile (2 x 64 cols)
    int m0   = blockIdx.y * 128;
    int n0   = blockIdx.x * 128;

    const __nv_bfloat16* Bh_g = g_Bh + (size_t)layer * 256 * KTOT;
    const __nv_bfloat16* Bl_g = g_Bl + (size_t)layer * 256 * KTOT;

    float acc[2][8][4];
#pragma unroll
    for (int i = 0; i < 2; i++)
#pragma unroll
        for (int j = 0; j < 8; j++)
#pragma unroll
            for (int q = 0; q < 4; q++) acc[i][j][q] = 0.f;

    // ---- async load of one 64-k chunk into buffer p ----
    // 4 arrays x 128 rows x 8 segs(16B) = 4096 segments, 16 per thread
    auto load_chunk = [&](int c, int p) {
        int k0 = c * 64;
        uint32_t dstb = sb + p * BUF_B;
#pragma unroll
        for (int i = 0; i < 16; i++) {
            int sid = tid + i * 256;          // 0..4095
            int arr = sid >> 10;              // 0:Ah 1:Al 2:Bh 3:Bl
            int s   = sid & 1023;
            int row = s >> 3;                 // 0..127
            int seg = s & 7;                  // 0..7 (8 els each)
            const __nv_bfloat16* srcp;
            if (arr < 2) {
                int grow = m0 + row; if (grow > Nn - 1) grow = Nn - 1;
                const __nv_bfloat16* base = (arr == 0) ? g_Ah : g_Al;
                srcp = base + (size_t)grow * KTOT + k0 + seg * 8;
            } else {
                const __nv_bfloat16* base = (arr == 2) ? Bh_g : Bl_g;
                srcp = base + (size_t)(n0 + row) * KTOT + k0 + seg * 8;
            }
            uint32_t dst = dstb + arr * ARR_B + row * (ROWP * 2) + seg * 16;
            CP_ASYNC16(dst, srcp);
        }
        CP_COMMIT();
    };

    load_chunk(0, 0);

    for (int c = 0; c < NCHUNK; c++) {
        int p = c & 1;
        if (c + 1 < NCHUNK) { load_chunk(c + 1, p ^ 1); CP_WAIT1(); }
        else                { CP_WAIT0(); }
        __syncthreads();

        const __nv_bfloat16* Ah = (const __nv_bfloat16*)(smem + p * BUF_B);
        const __nv_bfloat16* Al = (const __nv_bfloat16*)(smem + p * BUF_B + ARR_B);
        const __nv_bfloat16* Bh = (const __nv_bfloat16*)(smem + p * BUF_B + 2 * ARR_B);
        const __nv_bfloat16* Bl = (const __nv_bfloat16*)(smem + p * BUF_B + 3 * ARR_B);

#pragma unroll
        for (int ks = 0; ks < 4; ks++) {
            int kb = ks * 16 + tig * 2;
            uint32_t ah[2][4], al[2][4];
#pragma unroll
            for (int mt = 0; mt < 2; mt++) {
                int rb = wm * 32 + mt * 16;
                ah[mt][0] = *(const uint32_t*)&Ah[(rb + g)     * ROWP + kb];
                ah[mt][1] = *(const uint32_t*)&Ah[(rb + g + 8) * ROWP + kb];
                ah[mt][2] = *(const uint32_t*)&Ah[(rb + g)     * ROWP + kb + 8];
                ah[mt][3] = *(const uint32_t*)&Ah[(rb + g + 8) * ROWP + kb + 8];
                al[mt][0] = *(const uint32_t*)&Al[(rb + g)     * ROWP + kb];
                al[mt][1] = *(const uint32_t*)&Al[(rb + g + 8) * ROWP + kb];
                al[mt][2] = *(const uint32_t*)&Al[(rb + g)     * ROWP + kb + 8];
                al[mt][3] = *(const uint32_t*)&Al[(rb + g + 8) * ROWP + kb + 8];
            }
#pragma unroll
            for (int nt = 0; nt < 8; nt++) {
                int nb = wn * 64 + nt * 8;
                uint32_t bh0 = *(const uint32_t*)&Bh[(nb + g) * ROWP + kb];
                uint32_t bh1 = *(const uint32_t*)&Bh[(nb + g) * ROWP + kb + 8];
                uint32_t bl0 = *(const uint32_t*)&Bl[(nb + g) * ROWP + kb];
                uint32_t bl1 = *(const uint32_t*)&Bl[(nb + g) * ROWP + kb + 8];
#pragma unroll
                for (int mt = 0; mt < 2; mt++) {
                    mma_bf16(acc[mt][nt], ah[mt], bh0, bh1);   // hi*hi
                    mma_bf16(acc[mt][nt], ah[mt], bl0, bl1);   // hi*lo
                    mma_bf16(acc[mt][nt], al[mt], bh0, bh1);   // lo*hi
                }
            }
        }
        __syncthreads();
    }

    // ---- epilogue: bias + relu ----
#pragma unroll
    for (int mt = 0; mt < 2; mt++) {
        int row0 = m0 + wm * 32 + mt * 16 + g;
#pragma unroll
        for (int nt = 0; nt < 8; nt++) {
            int col = n0 + wn * 64 + nt * 8 + tig * 2;
            float b0 = bself[col], b1 = bself[col + 1];
            if (row0 < Nn) {
                float2 v;
                v.x = fmaxf(acc[mt][nt][0] + b0, 0.f);
                v.y = fmaxf(acc[mt][nt][1] + b1, 0.f);
                *(float2*)&hout[(size_t)row0 * D + col] = v;
            }
            if (row0 + 8 < Nn) {
                float2 v;
                v.x = fmaxf(acc[mt][nt][2] + b0, 0.f);
                v.y = fmaxf(acc[mt][nt][3] + b1, 0.f);
                *(float2*)&hout[(size_t)(row0 + 8) * D + col] = v;
            }
        }
    }
}

// ---------------- launch ----------------
extern "C" void kernel_launch(void* const* d_in, const int* in_sizes, int n_in,
                              void* d_out, int out_size) {
    const float* X     = (const float*)d_in[0];
    const int*   ntype = (const int*)d_in[1];
    const int*   ei    = (const int*)d_in[2];
    const int*   et    = (const int*)d_in[3];
    const float* aW    = (const float*)d_in[5];
    const float* ab    = (const float*)d_in[6];
    const float* Wrel  = (const float*)d_in[7];
    const float* Wself = (const float*)d_in[8];
    const float* bself = (const float*)d_in[9];
    float*       out   = (float*)d_out;

    int Nn = in_sizes[1];
    int E_ = in_sizes[3];

    void *ph = nullptr, *ph2 = nullptr;
    cudaGetSymbolAddress(&ph,  g_h);
    cudaGetSymbolAddress(&ph2, g_h2);

    cudaFuncSetAttribute(gemm_layer_mma, cudaFuncAttributeMaxDynamicSharedMemorySize, SMEM_TOTAL);

    int nb = (Nn + 255) / 256;
    k_init <<<nb, 256>>>(Nn);
    k_count<<<(E_ + 255) / 256, 256>>>(ei, E_);
    k_hist <<<nb, 256>>>(ntype, Nn);
    k_inv  <<<nb, 256>>>(Nn);
    k_offs <<<1, 1>>>();
    k_order<<<nb, 256>>>(ntype, Nn);
    k_transW<<<(NTYPE * DIN * D + 255) / 256, 256>>>(aW);
    k_packB<<<(2 * 256 * KTOT + 255) / 256, 256>>>(Wrel, Wself);

    adapt_gemm<<<dim3(2, (Nn + 63) / 64, NTYPE), 256>>>(X, ab, Nn);

    int total4  = NREL * Nn * (D / 4);
    int ntilesM = (Nn + 127) / 128;
    int convBlk = (Nn * (KTOT / 4) + 255) / 256;
    for (int l = 0; l < 2; l++) {
        const float* hin  = (l == 0) ? (const float*)ph : (const float*)ph2;
        float*       hout = (l == 0) ? (float*)ph2 : out;
        k_zero_tmp<<<4096, 256>>>(total4);
        k_scatter<<<(E_ + 7) / 8, 256>>>(ei, et, hin, E_, Nn);
        k_convA<<<convBlk, 256>>>(hin, Nn);
        gemm_layer_mma<<<dim3(2, ntilesM), 256, SMEM_TOTAL>>>(
            bself + (size_t)l * D, hout, Nn, l);
    }
}